// round 17
// baseline (speedup 1.0000x reference)
#include <cuda_runtime.h>
#include <cstdint>

#define NSP     2048
#define BATCH   64
#define NSTEP   1000
#define KEX     32            // steps between ghost exchanges
#define GW      64            // ghost width per side (= 2 * KEX)
#define OWNW    128           // owned elems per warp
#define COVER   256           // OWNW + 2*GW
#define EPT     8             // elems per thread (COVER/32)
#define THREADS 256           // 8 warps per CTA -> 2 warps/SMSP
#define OWN_CTA 1024          // owned per CTA (half row)
#define NSEG    32            // 31 full KEX segments + final 8-step segment

typedef unsigned long long u64;

__device__ __forceinline__ u64 pk(float lo, float hi) {
    u64 r; asm("mov.b64 %0,{%1,%2};" : "=l"(r) : "f"(lo), "f"(hi)); return r;
}
__device__ __forceinline__ void upk(u64 v, float& lo, float& hi) {
    asm("mov.b64 {%0,%1},%2;" : "=f"(lo), "=f"(hi) : "l"(v));
}
__device__ __forceinline__ u64 fma2(u64 a, u64 b, u64 c) {
    u64 d; asm("fma.rn.f32x2 %0,%1,%2,%3;" : "=l"(d) : "l"(a), "l"(b), "l"(c)); return d;
}
__device__ __forceinline__ u64 add2(u64 a, u64 b) {
    u64 d; asm("add.rn.f32x2 %0,%1,%2;" : "=l"(d) : "l"(a), "l"(b)); return d;
}
__device__ __forceinline__ u64 mul2(u64 a, u64 b) {
    u64 d; asm("mul.rn.f32x2 %0,%1,%2;" : "=l"(d) : "l"(a), "l"(b)); return d;
}

// branch-free predicated pair of 16B streaming stores (no BSSY/BSYNC)
__device__ __forceinline__ void st2_pred(int pred, float* p,
                                         u64 a, u64 b, u64 c, u64 d) {
    asm volatile(
        "{\n\t.reg .pred q;\n\t"
        "setp.ne.s32 q, %0, 0;\n\t"
        "@q st.global.cs.v2.u64 [%1], {%2,%3};\n\t"
        "@q st.global.cs.v2.u64 [%4], {%5,%6};\n\t}"
        :: "r"(pred), "l"(p), "l"(a), "l"(b), "l"(p + 4), "l"(c), "l"(d)
        : "memory");
}

// blocking parity wait, acquire at CLUSTER scope (peer's STS must be visible)
__device__ __forceinline__ void mbar_wait_acq_cluster(uint32_t addr, uint32_t parity) {
    asm volatile(
        "{\n\t.reg .pred P1;\n\t"
        "WL_%=:\n\t"
        "mbarrier.try_wait.parity.acquire.cluster.shared::cta.b64 P1, [%0], %1, 0x989680;\n\t"
        "@P1 bra.uni WD_%=;\n\t"
        "bra.uni WL_%=;\n\t"
        "WD_%=:\n\t}"
        :: "r"(addr), "r"(parity) : "memory");
}

__global__ void __cluster_dims__(2, 1, 1) __launch_bounds__(THREADS, 1)
ks_kernel(const float* __restrict__ u0,
          const float* __restrict__ cp,
          const float* __restrict__ ap,
          const float* __restrict__ bp,
          float* __restrict__ out) {
    __shared__ alignas(16) float sh_ex[2][OWN_CTA];   // double-buffered staging (8 KB)
    __shared__ alignas(8)  u64   mbar[2];             // one mbarrier per buffer parity

    const int row  = blockIdx.x >> 1;
    const int half = blockIdx.x & 1;
    const int w    = threadIdx.x >> 5;
    const int lane = threadIdx.x & 31;

    const float dt = 0.01f;
    const float Af = -0.5f * dt * (*cp);
    const float Bc = -dt * (*ap);
    const float Cc = -dt * (*bp);
    const float c0f = 1.0f - 2.0f * Bc + 6.0f * Cc;
    const float c1f = Bc - 4.0f * Cc;
    const u64 C0 = pk(c0f, c0f), C1 = pk(c1f, c1f), C2 = pk(Cc, Cc);
    const u64 AV = pk(Af, Af),   M1 = pk(-1.0f, -1.0f);

    const uint32_t shbase = (uint32_t)__cvta_generic_to_shared(&sh_ex[0][0]);
    const uint32_t mbbase = (uint32_t)__cvta_generic_to_shared(&mbar[0]);
    const uint32_t peer   = (uint32_t)(half ^ 1);

    if (threadIdx.x == 0) {
        asm volatile("mbarrier.init.shared.b64 [%0], 1;" :: "r"(mbbase)     : "memory");
        asm volatile("mbarrier.init.shared.b64 [%0], 1;" :: "r"(mbbase + 8) : "memory");
    }
    __syncthreads();
    asm volatile("barrier.cluster.arrive.aligned;" ::: "memory");
    asm volatile("barrier.cluster.wait.aligned;"   ::: "memory");

    // warp cover: local coord j in [0, COVER); global row pos = base + j (mod NSP)
    const int base = half * OWN_CTA + w * OWNW - GW;   // may be negative
    const int j0   = lane * EPT;

    // owned region [GW, GW+OWNW) = [64, 192) is lane-aligned: lanes 8..23
    const bool owned = (lane >= 8) && (lane < 24);
    const int  ownp  = owned ? 1 : 0;

    // ---- initial load: 2 float4 groups per thread, periodic wrap ----
    u64 P0, P1, P2, P3;
    {
        const float* urow = u0 + (size_t)row * NSP;
        int q0 = (base + j0)     & (NSP - 1);
        int q1 = (base + j0 + 4) & (NSP - 1);
        float4 v0 = *reinterpret_cast<const float4*>(urow + q0);
        float4 v1 = *reinterpret_cast<const float4*>(urow + q1);
        P0 = pk(v0.x, v0.y); P1 = pk(v0.z, v0.w);
        P2 = pk(v1.x, v1.y); P3 = pk(v1.z, v1.w);
    }

    // ---- frame 0 = u0 (owned lanes: fully coalesced, branch-free) ----
    st2_pred(ownp, out + (size_t)row * NSP + base + j0, P0, P1, P2, P3);

    const size_t FR = (size_t)BATCH * NSP;
    float* op = out + FR + (size_t)row * NSP + (base + j0);   // frame 1 cursor

    #pragma unroll 1
    for (int seg = 0; seg < NSEG; seg++) {
        if (seg > 0) {
            // ===== ghost exchange via mbarrier handshake (off hot path) =====
            const int n  = seg - 1;                         // exchange index
            const int q  = n & 1;                           // buffer parity
            const uint32_t ph = (uint32_t)((n >> 1) & 1);   // mbar[q] phase
            const uint32_t mb = mbbase + (uint32_t)(q * 8);

            // publish my owned 128 elems into sh_ex[q] (CTA index space)
            if (owned) {
                float a, b, c, d;
                float* s = &sh_ex[q][w * OWNW + (j0 - GW)];
                upk(P0, a, b); upk(P1, c, d);
                reinterpret_cast<float4*>(s)[0] = make_float4(a, b, c, d);
                upk(P2, a, b); upk(P3, c, d);
                reinterpret_cast<float4*>(s)[1] = make_float4(a, b, c, d);
            }
            __syncthreads();     // all local STS done + prior-exchange reads done

            // signal peer: my sh_ex[q] is ready (release at cluster scope)
            if (threadIdx.x == 0) {
                asm volatile(
                    "{\n\t.reg .b32 ra;\n\t"
                    "mapa.shared::cluster.u32 ra, %0, %1;\n\t"
                    "mbarrier.arrive.release.cluster.shared::cluster.b64 _, [ra];\n\t}"
                    :: "r"(mb), "r"(peer) : "memory");
            }
            mbar_wait_acq_cluster(mb, ph);

            // refill ghost lanes from own sh_ex[q] or peer sh_ex[q] (DSMEM)
            if (!owned) {
                #pragma unroll
                for (int g = 0; g < 2; g++) {
                    int pos = (base + j0 + 4 * g) & (NSP - 1);
                    int h2  = pos >> 10;            // owning half
                    int idx = pos & (OWN_CTA - 1);
                    float4 v;
                    if (h2 == half) {
                        v = *reinterpret_cast<const float4*>(&sh_ex[q][idx]);
                    } else {
                        uint32_t pa;
                        asm("mapa.shared::cluster.u32 %0, %1, %2;"
                            : "=r"(pa)
                            : "r"(shbase + (uint32_t)((q * OWN_CTA + idx) * 4)),
                              "r"(peer));
                        asm volatile("ld.shared::cluster.v4.f32 {%0,%1,%2,%3}, [%4];"
                                     : "=f"(v.x), "=f"(v.y), "=f"(v.z), "=f"(v.w)
                                     : "r"(pa));
                    }
                    if (g == 0) { P0 = pk(v.x, v.y); P1 = pk(v.z, v.w); }
                    else        { P2 = pk(v.x, v.y); P3 = pk(v.z, v.w); }
                }
            }
        }

        const int steps = (seg == NSEG - 1) ? (NSTEP - (NSEG - 1) * KEX) : KEX;
        #pragma unroll 4
        for (int s = 0; s < steps; s++) {
            // ===== one explicit-Euler step, registers + 2 u64 shuffles =====
            u64 prev = __shfl_up_sync(0xffffffffu, P3, 1);   // lane-1's edge pair
            u64 next = __shfl_down_sync(0xffffffffu, P0, 1); // lane+1's edge pair

            float a0, a1, a2, a3, a4, a5, a6, a7, a8, a9, aA, aB;
            upk(prev, a0, a1); upk(P0, a2, a3); upk(P1, a4, a5);
            upk(P2, a6, a7);   upk(P3, a8, a9); upk(next, aA, aB);
            u64 O0 = pk(a1, a2);
            u64 O1 = pk(a3, a4);
            u64 O2 = pk(a5, a6);
            u64 O3 = pk(a7, a8);
            u64 O4 = pk(a9, aA);

            u64 r0, r1, r2, r3;
            {   // pair 0: um2=prev, um1=O0, u=P0, up1=O1, up2=P1
                u64 d1 = fma2(M1, O0, O1);
                u64 t1 = fma2(AV, d1, C0);
                u64 s1 = add2(O1, O0);
                u64 s2 = add2(P1, prev);
                u64 m  = mul2(C2, s2);
                m      = fma2(C1, s1, m);
                r0     = fma2(P0, t1, m);
            }
            {   // pair 1: um2=P0, um1=O1, u=P1, up1=O2, up2=P2
                u64 d1 = fma2(M1, O1, O2);
                u64 t1 = fma2(AV, d1, C0);
                u64 s1 = add2(O2, O1);
                u64 s2 = add2(P2, P0);
                u64 m  = mul2(C2, s2);
                m      = fma2(C1, s1, m);
                r1     = fma2(P1, t1, m);
            }
            {   // pair 2: um2=P1, um1=O2, u=P2, up1=O3, up2=P3
                u64 d1 = fma2(M1, O2, O3);
                u64 t1 = fma2(AV, d1, C0);
                u64 s1 = add2(O3, O2);
                u64 s2 = add2(P3, P1);
                u64 m  = mul2(C2, s2);
                m      = fma2(C1, s1, m);
                r2     = fma2(P2, t1, m);
            }
            {   // pair 3: um2=P2, um1=O3, u=P3, up1=O4, up2=next
                u64 d1 = fma2(M1, O3, O4);
                u64 t1 = fma2(AV, d1, C0);
                u64 s1 = add2(O4, O3);
                u64 s2 = add2(next, P2);
                u64 m  = mul2(C2, s2);
                m      = fma2(C1, s1, m);
                r3     = fma2(P3, t1, m);
            }

            // trajectory frame: branch-free predicated coalesced stores
            st2_pred(ownp, op, r0, r1, r2, r3);
            op += FR;

            P0 = r0; P1 = r1; P2 = r2; P3 = r3;
        }
    }

    // don't exit while peer may still access our SMEM / mbarriers
    asm volatile("barrier.cluster.arrive.aligned;" ::: "memory");
    asm volatile("barrier.cluster.wait.aligned;"   ::: "memory");
}

extern "C" void kernel_launch(void* const* d_in, const int* in_sizes, int n_in,
                              void* d_out, int out_size) {
    const float* u0    = (const float*)d_in[0];
    const float* c     = (const float*)d_in[1];
    const float* alpha = (const float*)d_in[2];
    const float* beta  = (const float*)d_in[3];
    float* out = (float*)d_out;

    ks_kernel<<<BATCH * 2, THREADS>>>(u0, c, alpha, beta, out);
}